// round 1
// baseline (speedup 1.0000x reference)
#include <cuda_runtime.h>

// Problem constants
#define N_ROWS 32768          // 32*32*32 flattened rows
#define C_DIM  256            // embedding dim
#define K_DIM  1024           // num embeddings

// Output layout (flattened concatenation in return order)
#define OFF_QUANT 0
#define OFF_EMB   8388608
#define OFF_CS    8650752
#define OFF_DW    8651776
#define OFF_LOSS  8913920
#define OFF_PERP  8913921

// ------------------------- device scratch -------------------------
__device__ float  g_embT[K_DIM * C_DIM];   // [K, C] transposed embeddings
__device__ float  g_colnorm[K_DIM];        // ||e_k||^2
__device__ float  g_rownorm[N_ROWS];       // ||x_n||^2
__device__ float  g_pval[N_ROWS * 8];      // partial argmin values (8 col-blocks)
__device__ int    g_pidx[N_ROWS * 8];      // partial argmin indices
__device__ int    g_idx[N_ROWS];           // final assignment
__device__ int    g_counts[K_DIM];         // cluster histogram
__device__ float  g_smoothed[K_DIM];       // smoothed cluster size
__device__ double g_loss;                  // sum of (q - x)^2

// ------------------------- K0: init -------------------------
// out_dw <- ema_dw * 0.99 (atomically accumulated later), zero counts/loss
__global__ void k_init(const float* __restrict__ ema_dw, float* __restrict__ out_dw) {
    int i = blockIdx.x * blockDim.x + threadIdx.x;
    out_dw[i] = ema_dw[i] * 0.99f;
    if (i < K_DIM) g_counts[i] = 0;
    if (i == 0) g_loss = 0.0;
}

// ------------------------- K1: transpose embeddings [C,K] -> [K,C] ----------
__global__ void k_transpose(const float* __restrict__ emb) {
    __shared__ float t[32][33];
    int bx = blockIdx.x, by = blockIdx.y;       // bx over K tiles (32), by over C tiles (8)
    int tx = threadIdx.x, ty = threadIdx.y;     // 32 x 8
#pragma unroll
    for (int j = 0; j < 4; j++)
        t[ty + j * 8][tx] = emb[(by * 32 + ty + j * 8) * K_DIM + bx * 32 + tx];
    __syncthreads();
#pragma unroll
    for (int j = 0; j < 4; j++)
        g_embT[(bx * 32 + ty + j * 8) * C_DIM + by * 32 + tx] = t[tx][ty + j * 8];
}

// ------------------------- K2: column norms ||e_k||^2 -------------------------
__global__ void k_colnorm() {
    int w = threadIdx.x >> 5, lane = threadIdx.x & 31;
    int k = blockIdx.x * 8 + w;
    const float4* p = (const float4*)(g_embT + k * C_DIM);
    float4 a = p[lane];
    float4 b = p[lane + 32];
    float s = a.x * a.x + a.y * a.y + a.z * a.z + a.w * a.w
            + b.x * b.x + b.y * b.y + b.z * b.z + b.w * b.w;
#pragma unroll
    for (int o = 16; o; o >>= 1) s += __shfl_xor_sync(0xFFFFFFFFu, s, o);
    if (lane == 0) g_colnorm[k] = s;
}

// ------------------------- K3: row norms ||x_n||^2 -------------------------
__global__ void k_rownorm(const float* __restrict__ x) {
    int w = threadIdx.x >> 5, lane = threadIdx.x & 31;
    int n = blockIdx.x * 8 + w;
    const float4* p = (const float4*)(x + (size_t)n * C_DIM);
    float4 a = p[lane];
    float4 b = p[lane + 32];
    float s = a.x * a.x + a.y * a.y + a.z * a.z + a.w * a.w
            + b.x * b.x + b.y * b.y + b.z * b.z + b.w * b.w;
#pragma unroll
    for (int o = 16; o; o >>= 1) s += __shfl_xor_sync(0xFFFFFFFFu, s, o);
    if (lane == 0) g_rownorm[n] = s;
}

// ------------------------- K4: fp32 SGEMM (b = x.E) + fused per-block argmin ----
// M=32768, N=1024, Kc=256. 128x128 block tile, 8x8 per thread, k-chunk 8, dbuf.
// d = (rownorm - 2*b) + colnorm, fp32, exact association matching the reference.
__global__ __launch_bounds__(256, 2) void k_gemm_argmin(const float* __restrict__ A,
                                                        const float* __restrict__ B) {
    __shared__ float sm[4096];                 // 16 KB: As[2][8][128] | Bs[2][8][128]
    float* As = sm;
    float* Bs = sm + 2048;

    int tid = threadIdx.x;
    int bx = blockIdx.x;                       // N tile 0..7
    int by = blockIdx.y;                       // M tile 0..255
    int tx = tid & 15, ty = tid >> 4;

    int arow = tid >> 1;                       // 0..127
    int acol = (tid & 1) * 4;                  // 0 or 4
    const float* Aptr = A + ((size_t)(by * 128 + arow)) * 256 + acol;
    int brow = tid >> 5;                       // 0..7
    int bcol = (tid & 31) * 4;
    const float* Bptr = B + (size_t)brow * 1024 + bx * 128 + bcol;

    float acc[8][8];
#pragma unroll
    for (int i = 0; i < 8; i++)
#pragma unroll
        for (int j = 0; j < 8; j++) acc[i][j] = 0.f;

    // preload tile 0
    {
        float4 a = *(const float4*)(Aptr);
        float4 b = *(const float4*)(Bptr);
        As[(acol + 0) * 128 + arow] = a.x;
        As[(acol + 1) * 128 + arow] = a.y;
        As[(acol + 2) * 128 + arow] = a.z;
        As[(acol + 3) * 128 + arow] = a.w;
        *(float4*)&Bs[brow * 128 + bcol] = b;
    }
    __syncthreads();

    int buf = 0;
    for (int kb = 0; kb < 32; kb++) {
        float4 an, bn;
        if (kb < 31) {
            an = *(const float4*)(Aptr + (kb + 1) * 8);
            bn = *(const float4*)(Bptr + (size_t)(kb + 1) * 8 * 1024);
        }
        const float* Ab = As + buf * 1024;
        const float* Bb = Bs + buf * 1024;
#pragma unroll
        for (int kc = 0; kc < 8; kc++) {
            float4 a0 = *(const float4*)&Ab[kc * 128 + ty * 8];
            float4 a1 = *(const float4*)&Ab[kc * 128 + ty * 8 + 4];
            float4 b0 = *(const float4*)&Bb[kc * 128 + tx * 8];
            float4 b1 = *(const float4*)&Bb[kc * 128 + tx * 8 + 4];
            float av[8] = {a0.x, a0.y, a0.z, a0.w, a1.x, a1.y, a1.z, a1.w};
            float bv[8] = {b0.x, b0.y, b0.z, b0.w, b1.x, b1.y, b1.z, b1.w};
#pragma unroll
            for (int i = 0; i < 8; i++)
#pragma unroll
                for (int j = 0; j < 8; j++)
                    acc[i][j] = fmaf(av[i], bv[j], acc[i][j]);
        }
        if (kb < 31) {
            buf ^= 1;
            float* Aw = As + buf * 1024;
            float* Bw = Bs + buf * 1024;
            Aw[(acol + 0) * 128 + arow] = an.x;
            Aw[(acol + 1) * 128 + arow] = an.y;
            Aw[(acol + 2) * 128 + arow] = an.z;
            Aw[(acol + 3) * 128 + arow] = an.w;
            *(float4*)&Bw[brow * 128 + bcol] = bn;
            __syncthreads();
        }
    }

    // Epilogue: d = (rn - 2*acc) + cn, per-thread argmin over 8 cols, lowest-idx ties
    float rn[8], cn[8];
#pragma unroll
    for (int i = 0; i < 8; i++) rn[i] = g_rownorm[by * 128 + ty * 8 + i];
#pragma unroll
    for (int j = 0; j < 8; j++) cn[j] = g_colnorm[bx * 128 + tx * 8 + j];

    __syncthreads();                           // reuse smem for reduction
    float* rv = sm;                            // [128][16] values
    int*   ri = (int*)(sm + 2048);             // [128][16] indices

#pragma unroll
    for (int i = 0; i < 8; i++) {
        float best = 3.4e38f; int bj = 0;
#pragma unroll
        for (int j = 0; j < 8; j++) {
            float d = (rn[i] - 2.0f * acc[i][j]) + cn[j];
            if (d < best) { best = d; bj = j; }     // strict < keeps lowest j
        }
        rv[(ty * 8 + i) * 16 + tx] = best;
        ri[(ty * 8 + i) * 16 + tx] = bx * 128 + tx * 8 + bj;
    }
    __syncthreads();

    if (tid < 128) {
        float best = rv[tid * 16]; int bi = ri[tid * 16];
#pragma unroll
        for (int t = 1; t < 16; t++) {               // tx ascending == col ascending
            float v = rv[tid * 16 + t];
            if (v < best) { best = v; bi = ri[tid * 16 + t]; }
        }
        g_pval[(by * 128 + tid) * 8 + bx] = best;
        g_pidx[(by * 128 + tid) * 8 + bx] = bi;
    }
}

// ------------------------- K5: final argmin reduce + histogram ----------------
__global__ void k_reduce_idx() {
    int n = blockIdx.x * blockDim.x + threadIdx.x;
    float best = g_pval[n * 8]; int bi = g_pidx[n * 8];
#pragma unroll
    for (int t = 1; t < 8; t++) {                   // bx ascending == col ascending
        float v = g_pval[n * 8 + t];
        if (v < best) { best = v; bi = g_pidx[n * 8 + t]; }
    }
    g_idx[n] = bi;
    atomicAdd(&g_counts[bi], 1);
}

// ------------------------- K6: fused quant_st + loss + dw scatter -------------
// block = 256 threads (one per channel), 32 rows per block
__global__ void k_quant(const float* __restrict__ x,
                        float* __restrict__ out_quant,
                        float* __restrict__ out_dw) {
    int tid = threadIdx.x;
    int base = blockIdx.x * 32;
    float lsum = 0.f;
    for (int r = 0; r < 32; r++) {
        int n = base + r;
        int k = g_idx[n];
        float q  = g_embT[k * 256 + tid];
        float xv = x[(size_t)n * 256 + tid];
        float diff = q - xv;                         // fl(q - x), matches ref
        out_quant[(size_t)n * 256 + tid] = xv + diff; // x + (q - x), matches ref ST
        lsum += diff * diff;
        atomicAdd(&out_dw[tid * 1024 + k], 0.01f * xv);
    }
#pragma unroll
    for (int o = 16; o; o >>= 1) lsum += __shfl_xor_sync(0xFFFFFFFFu, lsum, o);
    __shared__ float ws[8];
    if ((tid & 31) == 0) ws[tid >> 5] = lsum;
    __syncthreads();
    if (tid < 8) {
        float v = ws[tid];
#pragma unroll
        for (int o = 4; o; o >>= 1) v += __shfl_xor_sync(0x000000FFu, v, o);
        if (tid == 0) atomicAdd(&g_loss, (double)v);
    }
}

// ------------------------- K7: EMA cs, n, smoothed, perplexity, loss ----------
__global__ void k_final(const float* __restrict__ ema_cs, float* __restrict__ out) {
    __shared__ float red[1024];
    int k = threadIdx.x;

    float cnt = (float)g_counts[k];
    float cs = ema_cs[k] * 0.99f + cnt * 0.01f;
    out[OFF_CS + k] = cs;

    red[k] = cs; __syncthreads();
    for (int s = 512; s > 0; s >>= 1) {
        if (k < s) red[k] += red[k + s];
        __syncthreads();
    }
    float n = red[0];
    __syncthreads();

    float p = cnt / 32768.0f;                        // exact (÷ 2^15)
    red[k] = p * logf(p + 1e-10f); __syncthreads();
    for (int s = 512; s > 0; s >>= 1) {
        if (k < s) red[k] += red[k + s];
        __syncthreads();
    }
    if (k == 0) {
        out[OFF_PERP] = expf(-red[0]);
        out[OFF_LOSS] = 0.25f * (float)(g_loss / 8388608.0);
    }
    g_smoothed[k] = (cs + 1e-5f) / (n + 0.01024f) * n;   // ((cs+eps)/(n+K*eps))*n
}

// ------------------------- K8: new embeddings = new_ema_dw / smoothed ---------
__global__ void k_newemb(float* __restrict__ out) {
    int i = blockIdx.x * blockDim.x + threadIdx.x;
    out[OFF_EMB + i] = out[OFF_DW + i] / g_smoothed[i & 1023];
}

// ------------------------- launch -------------------------
extern "C" void kernel_launch(void* const* d_in, const int* in_sizes, int n_in,
                              void* d_out, int out_size) {
    const float* x      = (const float*)d_in[0];   // inputs [32,32,32,256]
    const float* emb    = (const float*)d_in[1];   // embeddings [256,1024]
    const float* ema_cs = (const float*)d_in[2];   // [1024]
    const float* ema_dw = (const float*)d_in[3];   // [256,1024]
    float* out = (float*)d_out;

    k_init      <<<1024, 256>>>(ema_dw, out + OFF_DW);
    k_transpose <<<dim3(32, 8), dim3(32, 8)>>>(emb);
    k_colnorm   <<<128, 256>>>();
    k_rownorm   <<<4096, 256>>>(x);
    k_gemm_argmin<<<dim3(8, 256), 256>>>(x, emb);
    k_reduce_idx<<<128, 256>>>();
    k_quant     <<<1024, 256>>>(x, out + OFF_QUANT, out + OFF_DW);
    k_final     <<<1, 1024>>>(ema_cs, out);
    k_newemb    <<<1024, 256>>>(out);
}